// round 2
// baseline (speedup 1.0000x reference)
#include <cuda_runtime.h>
#include <cuda_bf16.h>
#include <math.h>
#include <stdint.h>

// ---------------- problem constants ----------------
#define H      3584
#define NH     28
#define NKV    4
#define D      128
#define GROUP  7           // NH / NKV
#define B      4
#define S      1024
#define T      (B*S)       // 4096
#define NB     512
#define BS     16
#define QKVD   ((NH + 2*NKV) * D)   // 4608
#define SCALE_ATT 0.08838834764831845f  // 1/sqrt(128)

#define CACHE_HALF ((size_t)NB * BS * NKV * D)   // 4,194,304 floats per (k|v)

// ---------------- scratch (device globals; no allocation allowed) ----------------
__device__ float g_qkv[(size_t)T * QKVD];       // 4096 x 4608
__device__ float g_ctx[(size_t)T * NH * D];     // 4096 x 3584

// ---------------------------------------------------------------------------
// Tensor-core GEMM:  C[M,N] = A[M,K] @ W[N,K]^T (+ bias[n])
// bf16 split-precision (hi/lo), 3 mma passes -> ~fp32-ish accuracy.
// Block tile 128x128, BK=32, 256 threads (8 warps, 4x2), warp tile 32x64.
// Requires M%128==0, N%128==0, K%32==0 (true for all uses here).
// ---------------------------------------------------------------------------
#define BMg 128
#define BNg 128
#define BKg 32
#define LDS_PAD 8   // bf16 elements of padding per row

__device__ __forceinline__ void mma16816(float c[4], const uint32_t a[4],
                                         const uint32_t b[2]) {
    asm volatile(
        "mma.sync.aligned.m16n8k16.row.col.f32.bf16.bf16.f32 "
        "{%0,%1,%2,%3}, {%4,%5,%6,%7}, {%8,%9}, {%0,%1,%2,%3};\n"
        : "+f"(c[0]), "+f"(c[1]), "+f"(c[2]), "+f"(c[3])
        : "r"(a[0]), "r"(a[1]), "r"(a[2]), "r"(a[3]), "r"(b[0]), "r"(b[1]));
}

__global__ __launch_bounds__(256, 2)
void gemm_mma_kernel(const float* __restrict__ A,
                     const float* __restrict__ W,
                     const float* __restrict__ bias,
                     float* __restrict__ C,
                     int M, int N, int K)
{
    __shared__ __nv_bfloat16 As_hi[BMg][BKg + LDS_PAD];
    __shared__ __nv_bfloat16 As_lo[BMg][BKg + LDS_PAD];
    __shared__ __nv_bfloat16 Ws_hi[BNg][BKg + LDS_PAD];
    __shared__ __nv_bfloat16 Ws_lo[BNg][BKg + LDS_PAD];

    const int tid  = threadIdx.x;
    const int m0   = blockIdx.y * BMg;
    const int n0   = blockIdx.x * BNg;
    const int warp = tid >> 5;
    const int lane = tid & 31;
    const int wm   = warp & 3;        // 0..3 -> rows wm*32
    const int wn   = warp >> 2;       // 0..1 -> cols wn*64
    const int grp  = lane >> 2;       // 0..7
    const int qp   = (lane & 3) * 2;  // 0,2,4,6

    // global-load assignment: row = tid/2 (0..127), 16-float half = tid&1
    const int lr = tid >> 1;
    const int lc = (tid & 1) * 16;

    float acc[2][8][4];
    #pragma unroll
    for (int mt = 0; mt < 2; mt++)
        #pragma unroll
        for (int j = 0; j < 8; j++)
            #pragma unroll
            for (int i = 0; i < 4; i++) acc[mt][j][i] = 0.f;

    for (int k0 = 0; k0 < K; k0 += BKg) {
        // ---- load + split A tile (128 x 32 floats) ----
        {
            const float4* src = (const float4*)&A[(size_t)(m0 + lr) * K + k0 + lc];
            #pragma unroll
            for (int u = 0; u < 4; u++) {
                float4 v = src[u];
                int c = lc + u * 4;
                float x[4] = {v.x, v.y, v.z, v.w};
                #pragma unroll
                for (int e = 0; e < 4; e++) {
                    __nv_bfloat16 hi = __float2bfloat16_rn(x[e]);
                    As_hi[lr][c + e] = hi;
                    As_lo[lr][c + e] = __float2bfloat16_rn(x[e] - __bfloat162float(hi));
                }
            }
        }
        // ---- load + split W tile (128 x 32 floats) ----
        {
            const float4* src = (const float4*)&W[(size_t)(n0 + lr) * K + k0 + lc];
            #pragma unroll
            for (int u = 0; u < 4; u++) {
                float4 v = src[u];
                int c = lc + u * 4;
                float x[4] = {v.x, v.y, v.z, v.w};
                #pragma unroll
                for (int e = 0; e < 4; e++) {
                    __nv_bfloat16 hi = __float2bfloat16_rn(x[e]);
                    Ws_hi[lr][c + e] = hi;
                    Ws_lo[lr][c + e] = __float2bfloat16_rn(x[e] - __bfloat162float(hi));
                }
            }
        }
        __syncthreads();

        #pragma unroll
        for (int kk = 0; kk < BKg; kk += 16) {
            // A fragments for the two 16-row tiles of this warp
            uint32_t ahi[2][4], alo[2][4];
            #pragma unroll
            for (int mt = 0; mt < 2; mt++) {
                int r = wm * 32 + mt * 16 + grp;
                ahi[mt][0] = *(const uint32_t*)&As_hi[r    ][kk + qp    ];
                ahi[mt][1] = *(const uint32_t*)&As_hi[r + 8][kk + qp    ];
                ahi[mt][2] = *(const uint32_t*)&As_hi[r    ][kk + qp + 8];
                ahi[mt][3] = *(const uint32_t*)&As_hi[r + 8][kk + qp + 8];
                alo[mt][0] = *(const uint32_t*)&As_lo[r    ][kk + qp    ];
                alo[mt][1] = *(const uint32_t*)&As_lo[r + 8][kk + qp    ];
                alo[mt][2] = *(const uint32_t*)&As_lo[r    ][kk + qp + 8];
                alo[mt][3] = *(const uint32_t*)&As_lo[r + 8][kk + qp + 8];
            }
            #pragma unroll
            for (int j = 0; j < 8; j++) {
                int n = wn * 64 + j * 8 + grp;
                uint32_t bhi[2], blo[2];
                bhi[0] = *(const uint32_t*)&Ws_hi[n][kk + qp    ];
                bhi[1] = *(const uint32_t*)&Ws_hi[n][kk + qp + 8];
                blo[0] = *(const uint32_t*)&Ws_lo[n][kk + qp    ];
                blo[1] = *(const uint32_t*)&Ws_lo[n][kk + qp + 8];
                mma16816(acc[0][j], ahi[0], bhi);
                mma16816(acc[1][j], ahi[1], bhi);
                mma16816(acc[0][j], alo[0], bhi);
                mma16816(acc[1][j], alo[1], bhi);
                mma16816(acc[0][j], ahi[0], blo);
                mma16816(acc[1][j], ahi[1], blo);
            }
        }
        __syncthreads();
    }

    // ---- epilogue: bias + store ----
    #pragma unroll
    for (int mt = 0; mt < 2; mt++) {
        int r0 = m0 + wm * 32 + mt * 16 + grp;
        #pragma unroll
        for (int j = 0; j < 8; j++) {
            int col = n0 + wn * 64 + j * 8 + qp;
            float b0 = 0.f, b1 = 0.f;
            if (bias) { b0 = bias[col]; b1 = bias[col + 1]; }
            float2 o0, o1;
            o0.x = acc[mt][j][0] + b0;
            o0.y = acc[mt][j][1] + b1;
            o1.x = acc[mt][j][2] + b0;
            o1.y = acc[mt][j][3] + b1;
            *(float2*)&C[(size_t)r0 * N + col]       = o0;
            *(float2*)&C[(size_t)(r0 + 8) * N + col] = o1;
        }
    }
}

// ---------------------------------------------------------------------------
// RoPE applied in-place to Q (NH heads) and K (NKV heads) sections of g_qkv.
// ---------------------------------------------------------------------------
__global__ void rope_kernel(const int* __restrict__ positions,
                            float* __restrict__ qkv)
{
    int idx = blockIdx.x * blockDim.x + threadIdx.x;
    const int total = T * (NH + NKV) * 64;
    if (idx >= total) return;
    int d    = idx & 63;
    int rest = idx >> 6;
    int head = rest % (NH + NKV);
    int t    = rest / (NH + NKV);

    float inv_freq = powf(10000.f, -(float)(2 * d) / 128.f);
    float ang = (float)positions[t] * inv_freq;
    float s, c;
    sincosf(ang, &s, &c);

    float* base = qkv + (size_t)t * QKVD + (size_t)head * D;
    float x1 = base[d];
    float x2 = base[d + 64];
    base[d]      = x1 * c - x2 * s;
    base[d + 64] = x2 * c + x1 * s;
}

// ---------------------------------------------------------------------------
// Copy the input kv_cache into the output cache region (float4 copy).
// ---------------------------------------------------------------------------
__global__ void cache_copy_kernel(const float4* __restrict__ src,
                                  float4* __restrict__ dst, int n4)
{
    int i = blockIdx.x * blockDim.x + threadIdx.x;
    if (i < n4) dst[i] = src[i];
}

// ---------------------------------------------------------------------------
// Scatter post-RoPE K and raw V into the output cache by slot_mapping.
// ---------------------------------------------------------------------------
__global__ void cache_scatter_kernel(const float* __restrict__ qkv,
                                     const int* __restrict__ slot_mapping,
                                     float* __restrict__ cache_out)
{
    int idx = blockIdx.x * blockDim.x + threadIdx.x;
    const int total = T * NKV * D;
    if (idx >= total) return;
    int d    = idx & (D - 1);
    int rest = idx >> 7;
    int kv   = rest & (NKV - 1);
    int t    = rest >> 2;

    int slot = slot_mapping[t];
    size_t src = (size_t)t * QKVD + (size_t)NH * D + (size_t)kv * D + d;
    size_t dst = ((size_t)slot * NKV + kv) * D + d;
    cache_out[dst]              = qkv[src];                     // K
    cache_out[CACHE_HALF + dst] = qkv[src + (size_t)NKV * D];   // V
}

// ---------------------------------------------------------------------------
// GQA causal attention, prefill. One warp per (token, kv-head); the warp
// processes all GROUP=7 query heads sharing that K/V, amortizing K/V loads 7x.
// Streaming online-softmax over keys 0..qi.
// ---------------------------------------------------------------------------
__global__ __launch_bounds__(256)
void attn_kernel(const float* __restrict__ qkv, float* __restrict__ ctx)
{
    int gw   = (blockIdx.x * blockDim.x + threadIdx.x) >> 5;
    int lane = threadIdx.x & 31;
    if (gw >= T * NKV) return;
    int t  = gw >> 2;          // token
    int kv = gw & 3;           // kv head
    int b  = t >> 10;          // t / S
    int qi = t & (S - 1);      // t % S

    // load 7 query heads (post-RoPE)
    float q[GROUP][4];
    {
        const float* qp = qkv + (size_t)t * QKVD + (size_t)kv * GROUP * D;
        #pragma unroll
        for (int g = 0; g < GROUP; g++)
            #pragma unroll
            for (int i = 0; i < 4; i++)
                q[g][i] = qp[g * D + lane + 32 * i];
    }

    const float* kbase = qkv + (size_t)(b << 10) * QKVD + (size_t)NH * D + (size_t)kv * D;
    const float* vbase = kbase + (size_t)NKV * D;

    float m[GROUP], l[GROUP], acc[GROUP][4];
    #pragma unroll
    for (int g = 0; g < GROUP; g++) {
        m[g] = -1e30f; l[g] = 0.f;
        #pragma unroll
        for (int i = 0; i < 4; i++) acc[g][i] = 0.f;
    }

    for (int s = 0; s <= qi; s++) {
        const float* kp = kbase + (size_t)s * QKVD;
        const float* vp = vbase + (size_t)s * QKVD;
        float k0 = kp[lane], k1 = kp[lane + 32], k2 = kp[lane + 64], k3 = kp[lane + 96];
        float v0 = vp[lane], v1 = vp[lane + 32], v2 = vp[lane + 64], v3 = vp[lane + 96];

        float dots[GROUP];
        #pragma unroll
        for (int g = 0; g < GROUP; g++)
            dots[g] = q[g][0] * k0 + q[g][1] * k1 + q[g][2] * k2 + q[g][3] * k3;

        // interleaved butterfly reductions (7-way ILP over the shfl chain)
        #pragma unroll
        for (int off = 16; off > 0; off >>= 1)
            #pragma unroll
            for (int g = 0; g < GROUP; g++)
                dots[g] += __shfl_xor_sync(0xffffffffu, dots[g], off);

        #pragma unroll
        for (int g = 0; g < GROUP; g++) {
            float sc = dots[g] * SCALE_ATT;
            if (sc > m[g]) {               // warp-uniform branch
                float corr = __expf(m[g] - sc);
                l[g] = l[g] * corr + 1.f;  // exp(sc-sc)=1
                acc[g][0] = acc[g][0] * corr + v0;
                acc[g][1] = acc[g][1] * corr + v1;
                acc[g][2] = acc[g][2] * corr + v2;
                acc[g][3] = acc[g][3] * corr + v3;
                m[g] = sc;
            } else {
                float p = __expf(sc - m[g]);
                l[g] += p;
                acc[g][0] += p * v0;
                acc[g][1] += p * v1;
                acc[g][2] += p * v2;
                acc[g][3] += p * v3;
            }
        }
    }

    #pragma unroll
    for (int g = 0; g < GROUP; g++) {
        float inv = 1.f / l[g];
        int h = kv * GROUP + g;
        float* op = ctx + (size_t)t * (NH * D) + (size_t)h * D;
        op[lane]      = acc[g][0] * inv;
        op[lane + 32] = acc[g][1] * inv;
        op[lane + 64] = acc[g][2] * inv;
        op[lane + 96] = acc[g][3] * inv;
    }
}

// ---------------------------------------------------------------------------
// launch
// ---------------------------------------------------------------------------
extern "C" void kernel_launch(void* const* d_in, const int* in_sizes, int n_in,
                              void* d_out, int out_size)
{
    const int*   positions    = (const int*)  d_in[0];
    const float* hidden       = (const float*)d_in[1];
    const float* kv_cache     = (const float*)d_in[2];
    const int*   slot_mapping = (const int*)  d_in[4];
    const int wb = n_in - 3;
    const float* w_qkv = (const float*)d_in[wb];
    const float* b_qkv = (const float*)d_in[wb + 1];
    const float* w_o   = (const float*)d_in[wb + 2];

    float* out       = (float*)d_out;
    float* cache_out = out + (size_t)T * H;

    float* qkv_buf = nullptr;
    float* ctx_buf = nullptr;
    cudaGetSymbolAddress((void**)&qkv_buf, g_qkv);
    cudaGetSymbolAddress((void**)&ctx_buf, g_ctx);

    // 1. QKV projection: [T, QKVD] = hidden [T,H] @ w_qkv[QKVD,H]^T + b
    {
        dim3 grid(QKVD / BNg, T / BMg);   // 36 x 32
        gemm_mma_kernel<<<grid, 256>>>(hidden, w_qkv, b_qkv, qkv_buf, T, QKVD, H);
    }

    // 2. RoPE on Q and K sections, in place
    {
        int total = T * (NH + NKV) * 64;
        rope_kernel<<<(total + 255) / 256, 256>>>(positions, qkv_buf);
    }

    // 3. Cache: copy original, then scatter new K/V
    {
        int n4 = (int)(2 * CACHE_HALF / 4);
        cache_copy_kernel<<<(n4 + 255) / 256, 256>>>((const float4*)kv_cache,
                                                     (float4*)cache_out, n4);
        int total = T * NKV * D;
        cache_scatter_kernel<<<(total + 255) / 256, 256>>>(qkv_buf, slot_mapping,
                                                           cache_out);
    }

    // 4. Attention -> ctx  (one warp per (token, kv head))
    {
        int warps = T * NKV;                       // 16384
        int threads = warps * 32;
        attn_kernel<<<(threads + 255) / 256, 256>>>(qkv_buf, ctx_buf);
    }

    // 5. Output projection: out [T,H] = ctx [T, NH*D] @ w_o[H, NH*D]^T
    {
        dim3 grid(H / BNg, T / BMg);      // 28 x 32
        gemm_mma_kernel<<<grid, 256>>>(ctx_buf, w_o, nullptr, out, T, H, NH * D);
    }
}

// round 5
// speedup vs baseline: 1.9026x; 1.9026x over previous
#include <cuda_runtime.h>
#include <cuda_bf16.h>
#include <math.h>
#include <stdint.h>

// ---------------- problem constants ----------------
#define H      3584
#define NH     28
#define NKV    4
#define D      128
#define GROUP  7           // NH / NKV
#define B      4
#define S      1024
#define T      (B*S)       // 4096
#define NB     512
#define BS     16
#define QKVD   ((NH + 2*NKV) * D)   // 4608
#define SCALE_ATT 0.08838834764831845f  // 1/sqrt(128)

#define CACHE_HALF ((size_t)NB * BS * NKV * D)   // 4,194,304 floats per (k|v)

// ---------------- scratch (device globals; no allocation allowed) ----------------
__device__ float g_qkv[(size_t)T * QKVD];       // fp32, post-RoPE
__device__ float g_ctx[(size_t)T * NH * D];     // fp32

__device__ __nv_bfloat16 g_hid_hi[(size_t)T * H];
__device__ __nv_bfloat16 g_hid_lo[(size_t)T * H];
__device__ __nv_bfloat16 g_wqkv_hi[(size_t)QKVD * H];
__device__ __nv_bfloat16 g_wqkv_lo[(size_t)QKVD * H];
__device__ __nv_bfloat16 g_wo_hi[(size_t)H * NH * D];
__device__ __nv_bfloat16 g_wo_lo[(size_t)H * NH * D];
__device__ __nv_bfloat16 g_ctx_hi[(size_t)T * NH * D];
__device__ __nv_bfloat16 g_ctx_lo[(size_t)T * NH * D];

// ============================================================================
// Split fp32 -> (bf16 hi, bf16 lo): bandwidth-bound, OUT of the GEMM loop.
// ============================================================================
__global__ void split_kernel(const float4* __restrict__ src,
                             __nv_bfloat162* __restrict__ hi,
                             __nv_bfloat162* __restrict__ lo, int n4)
{
    int i = blockIdx.x * blockDim.x + threadIdx.x;
    if (i >= n4) return;
    float4 v = src[i];
    __nv_bfloat16 h0 = __float2bfloat16_rn(v.x);
    __nv_bfloat16 h1 = __float2bfloat16_rn(v.y);
    __nv_bfloat16 h2 = __float2bfloat16_rn(v.z);
    __nv_bfloat16 h3 = __float2bfloat16_rn(v.w);
    __nv_bfloat16 l0 = __float2bfloat16_rn(v.x - __bfloat162float(h0));
    __nv_bfloat16 l1 = __float2bfloat16_rn(v.y - __bfloat162float(h1));
    __nv_bfloat16 l2 = __float2bfloat16_rn(v.z - __bfloat162float(h2));
    __nv_bfloat16 l3 = __float2bfloat16_rn(v.w - __bfloat162float(h3));
    hi[2 * i]     = __nv_bfloat162(h0, h1);
    hi[2 * i + 1] = __nv_bfloat162(h2, h3);
    lo[2 * i]     = __nv_bfloat162(l0, l1);
    lo[2 * i + 1] = __nv_bfloat162(l2, l3);
}

// ============================================================================
// Tensor-core GEMM (mma.sync — the only tensor path the harness build allows;
// tcgen05 requires sm_103a-suffixed target which the harness compiles without):
// C[M,N] = A[M,K] @ W[N,K]^T (+bias).  A/W pre-split bf16 hi/lo in GMEM.
// 3 mma passes per fragment: hi*hi + lo*hi + hi*lo -> ~fp32 accuracy.
// Block tile 128x128, BK=32, 256 threads (8 warps 4x2), warp tile 32x64.
// ============================================================================
#define BMg 128
#define BNg 128
#define BKg 32
#define LDS_PAD 8   // bf16 elems; row = 40 elems = 80 B (16B-aligned slots)

__device__ __forceinline__ void mma16816(float c[4], const uint32_t a[4],
                                         const uint32_t b[2]) {
    asm volatile(
        "mma.sync.aligned.m16n8k16.row.col.f32.bf16.bf16.f32 "
        "{%0,%1,%2,%3}, {%4,%5,%6,%7}, {%8,%9}, {%0,%1,%2,%3};\n"
        : "+f"(c[0]), "+f"(c[1]), "+f"(c[2]), "+f"(c[3])
        : "r"(a[0]), "r"(a[1]), "r"(a[2]), "r"(a[3]), "r"(b[0]), "r"(b[1]));
}

__global__ __launch_bounds__(256, 2)
void gemm_mma_kernel(const __nv_bfloat16* __restrict__ Ahi,
                     const __nv_bfloat16* __restrict__ Alo,
                     const __nv_bfloat16* __restrict__ Whi,
                     const __nv_bfloat16* __restrict__ Wlo,
                     const float* __restrict__ bias,
                     float* __restrict__ C,
                     int M, int N, int K)
{
    __shared__ __nv_bfloat16 As_hi[BMg][BKg + LDS_PAD];
    __shared__ __nv_bfloat16 As_lo[BMg][BKg + LDS_PAD];
    __shared__ __nv_bfloat16 Ws_hi[BNg][BKg + LDS_PAD];
    __shared__ __nv_bfloat16 Ws_lo[BNg][BKg + LDS_PAD];

    const int tid  = threadIdx.x;
    const int m0   = blockIdx.y * BMg;
    const int n0   = blockIdx.x * BNg;
    const int warp = tid >> 5;
    const int lane = tid & 31;
    const int wm   = warp & 3;        // 0..3 -> rows wm*32
    const int wn   = warp >> 2;       // 0..1 -> cols wn*64
    const int grp  = lane >> 2;       // 0..7
    const int qp   = (lane & 3) * 2;  // 0,2,4,6

    // global-load assignment: row = tid/2, 16-bf16 half = tid&1
    // Each thread covers 16 bf16 = 32 bytes = TWO uint4 per array.
    const int lr = tid >> 1;
    const int lc = (tid & 1) * 16;
    const size_t arow = (size_t)(m0 + lr) * K + lc;
    const size_t brow = (size_t)(n0 + lr) * K + lc;

    float acc[2][8][4];
    #pragma unroll
    for (int mt = 0; mt < 2; mt++)
        #pragma unroll
        for (int j = 0; j < 8; j++)
            #pragma unroll
            for (int i = 0; i < 4; i++) acc[mt][j][i] = 0.f;

    for (int k0 = 0; k0 < K; k0 += BKg) {
        // ---- stage tiles: 8 x uint4 per thread, no conversions ----
        uint4 vah0 = *(const uint4*)&Ahi[arow + k0];
        uint4 vah1 = *(const uint4*)&Ahi[arow + k0 + 8];
        uint4 val0 = *(const uint4*)&Alo[arow + k0];
        uint4 val1 = *(const uint4*)&Alo[arow + k0 + 8];
        uint4 vwh0 = *(const uint4*)&Whi[brow + k0];
        uint4 vwh1 = *(const uint4*)&Whi[brow + k0 + 8];
        uint4 vwl0 = *(const uint4*)&Wlo[brow + k0];
        uint4 vwl1 = *(const uint4*)&Wlo[brow + k0 + 8];
        *(uint4*)&As_hi[lr][lc]     = vah0;
        *(uint4*)&As_hi[lr][lc + 8] = vah1;
        *(uint4*)&As_lo[lr][lc]     = val0;
        *(uint4*)&As_lo[lr][lc + 8] = val1;
        *(uint4*)&Ws_hi[lr][lc]     = vwh0;
        *(uint4*)&Ws_hi[lr][lc + 8] = vwh1;
        *(uint4*)&Ws_lo[lr][lc]     = vwl0;
        *(uint4*)&Ws_lo[lr][lc + 8] = vwl1;
        __syncthreads();

        #pragma unroll
        for (int kk = 0; kk < BKg; kk += 16) {
            uint32_t ahi[2][4], alo[2][4];
            #pragma unroll
            for (int mt = 0; mt < 2; mt++) {
                int r = wm * 32 + mt * 16 + grp;
                ahi[mt][0] = *(const uint32_t*)&As_hi[r    ][kk + qp    ];
                ahi[mt][1] = *(const uint32_t*)&As_hi[r + 8][kk + qp    ];
                ahi[mt][2] = *(const uint32_t*)&As_hi[r    ][kk + qp + 8];
                ahi[mt][3] = *(const uint32_t*)&As_hi[r + 8][kk + qp + 8];
                alo[mt][0] = *(const uint32_t*)&As_lo[r    ][kk + qp    ];
                alo[mt][1] = *(const uint32_t*)&As_lo[r + 8][kk + qp    ];
                alo[mt][2] = *(const uint32_t*)&As_lo[r    ][kk + qp + 8];
                alo[mt][3] = *(const uint32_t*)&As_lo[r + 8][kk + qp + 8];
            }
            #pragma unroll
            for (int j = 0; j < 8; j++) {
                int n = wn * 64 + j * 8 + grp;
                uint32_t bhi[2], blo[2];
                bhi[0] = *(const uint32_t*)&Ws_hi[n][kk + qp    ];
                bhi[1] = *(const uint32_t*)&Ws_hi[n][kk + qp + 8];
                blo[0] = *(const uint32_t*)&Ws_lo[n][kk + qp    ];
                blo[1] = *(const uint32_t*)&Ws_lo[n][kk + qp + 8];
                mma16816(acc[0][j], ahi[0], bhi);
                mma16816(acc[1][j], ahi[1], bhi);
                mma16816(acc[0][j], alo[0], bhi);
                mma16816(acc[1][j], alo[1], bhi);
                mma16816(acc[0][j], ahi[0], blo);
                mma16816(acc[1][j], ahi[1], blo);
            }
        }
        __syncthreads();
    }

    // ---- epilogue: bias + store ----
    #pragma unroll
    for (int mt = 0; mt < 2; mt++) {
        int r0 = m0 + wm * 32 + mt * 16 + grp;
        #pragma unroll
        for (int j = 0; j < 8; j++) {
            int col = n0 + wn * 64 + j * 8 + qp;
            float b0 = 0.f, b1 = 0.f;
            if (bias) { b0 = bias[col]; b1 = bias[col + 1]; }
            float2 o0, o1;
            o0.x = acc[mt][j][0] + b0;
            o0.y = acc[mt][j][1] + b1;
            o1.x = acc[mt][j][2] + b0;
            o1.y = acc[mt][j][3] + b1;
            *(float2*)&C[(size_t)r0 * N + col]       = o0;
            *(float2*)&C[(size_t)(r0 + 8) * N + col] = o1;
        }
    }
}

// ---------------------------------------------------------------------------
// RoPE applied in-place to Q (NH heads) and K (NKV heads) sections of g_qkv.
// ---------------------------------------------------------------------------
__global__ void rope_kernel(const int* __restrict__ positions,
                            float* __restrict__ qkv)
{
    int idx = blockIdx.x * blockDim.x + threadIdx.x;
    const int total = T * (NH + NKV) * 64;
    if (idx >= total) return;
    int d    = idx & 63;
    int rest = idx >> 6;
    int head = rest % (NH + NKV);
    int t    = rest / (NH + NKV);

    float inv_freq = powf(10000.f, -(float)(2 * d) / 128.f);
    float ang = (float)positions[t] * inv_freq;
    float s, c;
    sincosf(ang, &s, &c);

    float* base = qkv + (size_t)t * QKVD + (size_t)head * D;
    float x1 = base[d];
    float x2 = base[d + 64];
    base[d]      = x1 * c - x2 * s;
    base[d + 64] = x2 * c + x1 * s;
}

// ---------------------------------------------------------------------------
// Copy the input kv_cache into the output cache region (float4 copy).
// ---------------------------------------------------------------------------
__global__ void cache_copy_kernel(const float4* __restrict__ src,
                                  float4* __restrict__ dst, int n4)
{
    int i = blockIdx.x * blockDim.x + threadIdx.x;
    if (i < n4) dst[i] = src[i];
}

// ---------------------------------------------------------------------------
// Scatter post-RoPE K and raw V into the output cache by slot_mapping.
// ---------------------------------------------------------------------------
__global__ void cache_scatter_kernel(const float* __restrict__ qkv,
                                     const int* __restrict__ slot_mapping,
                                     float* __restrict__ cache_out)
{
    int idx = blockIdx.x * blockDim.x + threadIdx.x;
    const int total = T * NKV * D;
    if (idx >= total) return;
    int d    = idx & (D - 1);
    int rest = idx >> 7;
    int kv   = rest & (NKV - 1);
    int t    = rest >> 2;

    int slot = slot_mapping[t];
    size_t src = (size_t)t * QKVD + (size_t)NH * D + (size_t)kv * D + d;
    size_t dst = ((size_t)slot * NKV + kv) * D + d;
    cache_out[dst]              = qkv[src];                     // K
    cache_out[CACHE_HALF + dst] = qkv[src + (size_t)NKV * D];   // V
}

// ---------------------------------------------------------------------------
// GQA causal attention, prefill. One warp per (token, kv-head); processes all
// GROUP=7 query heads sharing that K/V. Streaming online-softmax.
// ---------------------------------------------------------------------------
__global__ __launch_bounds__(256)
void attn_kernel(const float* __restrict__ qkv, float* __restrict__ ctx)
{
    int gw   = (blockIdx.x * blockDim.x + threadIdx.x) >> 5;
    int lane = threadIdx.x & 31;
    if (gw >= T * NKV) return;
    int t  = gw >> 2;
    int kv = gw & 3;
    int b  = t >> 10;
    int qi = t & (S - 1);

    float q[GROUP][4];
    {
        const float* qp = qkv + (size_t)t * QKVD + (size_t)kv * GROUP * D;
        #pragma unroll
        for (int g = 0; g < GROUP; g++)
            #pragma unroll
            for (int i = 0; i < 4; i++)
                q[g][i] = qp[g * D + lane + 32 * i];
    }

    const float* kbase = qkv + (size_t)(b << 10) * QKVD + (size_t)NH * D + (size_t)kv * D;
    const float* vbase = kbase + (size_t)NKV * D;

    float m[GROUP], l[GROUP], acc[GROUP][4];
    #pragma unroll
    for (int g = 0; g < GROUP; g++) {
        m[g] = -1e30f; l[g] = 0.f;
        #pragma unroll
        for (int i = 0; i < 4; i++) acc[g][i] = 0.f;
    }

    for (int s = 0; s <= qi; s++) {
        const float* kp = kbase + (size_t)s * QKVD;
        const float* vp = vbase + (size_t)s * QKVD;
        float k0 = kp[lane], k1 = kp[lane + 32], k2 = kp[lane + 64], k3 = kp[lane + 96];
        float v0 = vp[lane], v1 = vp[lane + 32], v2 = vp[lane + 64], v3 = vp[lane + 96];

        float dots[GROUP];
        #pragma unroll
        for (int g = 0; g < GROUP; g++)
            dots[g] = q[g][0] * k0 + q[g][1] * k1 + q[g][2] * k2 + q[g][3] * k3;

        #pragma unroll
        for (int off = 16; off > 0; off >>= 1)
            #pragma unroll
            for (int g = 0; g < GROUP; g++)
                dots[g] += __shfl_xor_sync(0xffffffffu, dots[g], off);

        #pragma unroll
        for (int g = 0; g < GROUP; g++) {
            float sc = dots[g] * SCALE_ATT;
            if (sc > m[g]) {
                float corr = __expf(m[g] - sc);
                l[g] = l[g] * corr + 1.f;
                acc[g][0] = acc[g][0] * corr + v0;
                acc[g][1] = acc[g][1] * corr + v1;
                acc[g][2] = acc[g][2] * corr + v2;
                acc[g][3] = acc[g][3] * corr + v3;
                m[g] = sc;
            } else {
                float p = __expf(sc - m[g]);
                l[g] += p;
                acc[g][0] += p * v0;
                acc[g][1] += p * v1;
                acc[g][2] += p * v2;
                acc[g][3] += p * v3;
            }
        }
    }

    #pragma unroll
    for (int g = 0; g < GROUP; g++) {
        float inv = 1.f / l[g];
        int h = kv * GROUP + g;
        float* op = ctx + (size_t)t * (NH * D) + (size_t)h * D;
        op[lane]      = acc[g][0] * inv;
        op[lane + 32] = acc[g][1] * inv;
        op[lane + 64] = acc[g][2] * inv;
        op[lane + 96] = acc[g][3] * inv;
    }
}

// ---------------------------------------------------------------------------
// launch
// ---------------------------------------------------------------------------
extern "C" void kernel_launch(void* const* d_in, const int* in_sizes, int n_in,
                              void* d_out, int out_size)
{
    const int*   positions    = (const int*)  d_in[0];
    const float* hidden       = (const float*)d_in[1];
    const float* kv_cache     = (const float*)d_in[2];
    const int*   slot_mapping = (const int*)  d_in[4];
    const int wb = n_in - 3;
    const float* w_qkv = (const float*)d_in[wb];
    const float* b_qkv = (const float*)d_in[wb + 1];
    const float* w_o   = (const float*)d_in[wb + 2];

    float* out       = (float*)d_out;
    float* cache_out = out + (size_t)T * H;

    float *qkv_buf, *ctx_buf;
    __nv_bfloat16 *hid_hi, *hid_lo, *wqkv_hi, *wqkv_lo, *wo_hi, *wo_lo, *ctx_hi, *ctx_lo;
    cudaGetSymbolAddress((void**)&qkv_buf, g_qkv);
    cudaGetSymbolAddress((void**)&ctx_buf, g_ctx);
    cudaGetSymbolAddress((void**)&hid_hi, g_hid_hi);
    cudaGetSymbolAddress((void**)&hid_lo, g_hid_lo);
    cudaGetSymbolAddress((void**)&wqkv_hi, g_wqkv_hi);
    cudaGetSymbolAddress((void**)&wqkv_lo, g_wqkv_lo);
    cudaGetSymbolAddress((void**)&wo_hi, g_wo_hi);
    cudaGetSymbolAddress((void**)&wo_lo, g_wo_lo);
    cudaGetSymbolAddress((void**)&ctx_hi, g_ctx_hi);
    cudaGetSymbolAddress((void**)&ctx_lo, g_ctx_lo);

    // 0) cache copy (independent of everything)
    {
        int n4 = (int)(2 * CACHE_HALF / 4);
        cache_copy_kernel<<<(n4 + 255) / 256, 256>>>((const float4*)kv_cache,
                                                     (float4*)cache_out, n4);
    }

    // 1) splits: hidden + w_qkv (needed first), then w_o (needed later)
    {
        int nh4 = (T * H) / 4;
        split_kernel<<<(nh4 + 255) / 256, 256>>>((const float4*)hidden,
            (__nv_bfloat162*)hid_hi, (__nv_bfloat162*)hid_lo, nh4);
        int nw4 = (QKVD * H) / 4;
        split_kernel<<<(nw4 + 255) / 256, 256>>>((const float4*)w_qkv,
            (__nv_bfloat162*)wqkv_hi, (__nv_bfloat162*)wqkv_lo, nw4);
        int no4 = (H * NH * D) / 4;
        split_kernel<<<(no4 + 255) / 256, 256>>>((const float4*)w_o,
            (__nv_bfloat162*)wo_hi, (__nv_bfloat162*)wo_lo, no4);
    }

    // 2) QKV projection: [T,QKVD] = hid @ w_qkv^T + b
    {
        dim3 grid(QKVD / BNg, T / BMg);   // 36 x 32
        gemm_mma_kernel<<<grid, 256>>>(hid_hi, hid_lo, wqkv_hi, wqkv_lo,
                                       b_qkv, qkv_buf, T, QKVD, H);
    }

    // 3) RoPE (in place on Q,K)
    {
        int total = T * (NH + NKV) * 64;
        rope_kernel<<<(total + 255) / 256, 256>>>(positions, qkv_buf);
    }

    // 4) cache scatter (needs post-RoPE K)
    {
        int total = T * NKV * D;
        cache_scatter_kernel<<<(total + 255) / 256, 256>>>(qkv_buf, slot_mapping,
                                                           cache_out);
    }

    // 5) attention -> ctx (fp32)
    {
        int warps = T * NKV;
        int threads = warps * 32;
        attn_kernel<<<(threads + 255) / 256, 256>>>(qkv_buf, ctx_buf);
    }

    // 6) split ctx
    {
        int n4 = (T * NH * D) / 4;
        split_kernel<<<(n4 + 255) / 256, 256>>>((const float4*)ctx_buf,
            (__nv_bfloat162*)ctx_hi, (__nv_bfloat162*)ctx_lo, n4);
    }

    // 7) output projection: out[T,H] = ctx @ w_o^T
    {
        dim3 grid(H / BNg, T / BMg);      // 28 x 32
        gemm_mma_kernel<<<grid, 256>>>(ctx_hi, ctx_lo, wo_hi, wo_lo,
                                       nullptr, out, T, H, NH * D);
    }
}